// round 6
// baseline (speedup 1.0000x reference)
#include <cuda_runtime.h>
#include <cuda_bf16.h>

// AbsolutePositionEncoding: out[b][s][e] = E[s/8][e], b<64, s<2048, e<256 (fp32)
// Only objects 0..255 are referenced (2048/8 = 256), though E has 512 rows.
//
// Pure broadcast-write kernel: 128 MiB stores, ~2 MB reads -> HBM-write-bound,
// floor ~17 us @ 8 TB/s.
//
// Grid (256, 2): blockIdx.x = object, blockIdx.y = batch half (32 batches).
// Thread t holds ONE float4 of the object's row in a register (lane = t & 63;
// t and t+256 are congruent mod 64, so one value serves both positions) and
// stores it 64 times. Stores are warp-contiguous 512B bursts (STG.E.128).

__global__ __launch_bounds__(256, 8)
void ape_broadcast_kernel(const float4* __restrict__ E4, float4* __restrict__ out4) {
    const int obj = blockIdx.x;              // 0..255
    const int t   = threadIdx.x;             // 0..255
    const int b0  = blockIdx.y * 32;         // starting batch (0 or 32)

    // Row of E for this object: 256 floats = 64 float4. Lane repeats mod 64.
    const float4 v = E4[obj * 64 + (t & 63)];

    // Per-batch stride = 2048*256/4 = 131072 f4. Object span within a batch:
    // obj*8 tokens * 64 f4/token = obj*512, length 512 f4 (256 objs * 512 = 131072 ✓).
    float4* base = out4 + (size_t)b0 * 131072 + obj * 512 + t;

    #pragma unroll
    for (int b = 0; b < 32; ++b) {
        float4* p = base + (size_t)b * 131072;
        p[0]   = v;   // j = t
        p[256] = v;   // j = t + 256
    }
}

extern "C" void kernel_launch(void* const* d_in, const int* in_sizes, int n_in,
                              void* d_out, int out_size) {
    // d_in[0] = x (unused), d_in[1] = E_absolute_position [512, 256] fp32
    const float4* E4 = (const float4*)d_in[1];
    float4* out4 = (float4*)d_out;
    dim3 grid(256, 2);
    ape_broadcast_kernel<<<grid, 256>>>(E4, out4);
}

// round 7
// speedup vs baseline: 1.0920x; 1.0920x over previous
#include <cuda_runtime.h>
#include <cuda_bf16.h>

// AbsolutePositionEncoding: out[b][s][e] = E[s/8][e], b<64, s<2048, e<256 (fp32)
// Only objects 0..255 referenced (2048/8). Pure broadcast-write: 128 MiB stores.
//
// R6: concurrency fix. R5 showed DRAM=40.6% with occ=30.2% — write bandwidth
// was bound by outstanding-store credits across too few warps (3.46 CTAs/SM).
// Grid (256, 4) = 1024 blocks = ~6.9 CTAs/SM, single wave (capacity 8/SM),
// ~86% occupancy. Each thread: one float4 register, 32 warp-contiguous
// STG.E.128 (512B bursts).

__global__ __launch_bounds__(256, 8)
void ape_broadcast_kernel(const float4* __restrict__ E4, float4* __restrict__ out4) {
    const int obj = blockIdx.x;              // 0..255
    const int t   = threadIdx.x;             // 0..255
    const int b0  = blockIdx.y * 16;         // starting batch: 0,16,32,48

    // Row of E for this object: 256 floats = 64 float4. Lane repeats mod 64
    // (t and t+256 congruent mod 64 -> one register serves both positions).
    const float4 v = E4[obj * 64 + (t & 63)];

    // Per-batch stride = 2048*256/4 = 131072 f4. Object span within a batch:
    // obj*512 f4, length 512 f4 (256 objs * 512 = 131072 = full batch slice).
    float4* base = out4 + (size_t)b0 * 131072 + obj * 512 + t;

    #pragma unroll
    for (int b = 0; b < 16; ++b) {
        float4* p = base + (size_t)b * 131072;
        p[0]   = v;   // j = t
        p[256] = v;   // j = t + 256
    }
}

extern "C" void kernel_launch(void* const* d_in, const int* in_sizes, int n_in,
                              void* d_out, int out_size) {
    // d_in[0] = x (unused), d_in[1] = E_absolute_position [512, 256] fp32
    const float4* E4 = (const float4*)d_in[1];
    float4* out4 = (float4*)d_out;
    dim3 grid(256, 4);
    ape_broadcast_kernel<<<grid, 256>>>(E4, out4);
}